// round 11
// baseline (speedup 1.0000x reference)
#include <cuda_runtime.h>
#include <math.h>

// ---------------------------------------------------------------------------
// CascadeGCN: 2-layer GCN, N=100000, c_in=5, hid=32, c_out=1.
// R11: single persistent kernel, 4 phases separated by a software grid
//      barrier (eliminates 4 inter-kernel gaps + the memset node).
//   ph1 fill:    bkt[d][slot++] = s      (g_cnt==0 invariant at entry)
//   ph2 prep:    xs[i] = x[i]*dinv[i]
//   ph3 gather1: aggx=xs[i]+sum xs[bkt]; h=relu(dv*(aggx@W1)+b1); t2=dv*(h@W2)
//   ph4 gather2: z=t2[i]+sum t2[bkt]; out=sigmoid(z*dv+b2); g_cnt[i]=0
// ---------------------------------------------------------------------------

#define NMAX 100000
#define CIN 5
#define HID 32
#define CAP 80    // max in-degree: Poisson(25), P(any node >= 80) ~ e^-33
#define BLK 1024

__device__ __align__(16) int   g_cnt [NMAX];            // zero at entry/exit
__device__ __align__(16) float g_dinv[NMAX];
__device__ __align__(16) int   g_bkt [NMAX * CAP + 32];
__device__ __align__(16) float g_xs  [NMAX * 8];
__device__ __align__(16) float g_t2  [NMAX];
__device__ int          g_bar_in;
__device__ volatile int g_gen;

// --- software grid barrier (generation counted) -----------------------------
__device__ __forceinline__ void gbar(int nblocks) {
    __threadfence();             // release this thread's writes
    __syncthreads();
    if (threadIdx.x == 0) {
        int gen = g_gen;
        if (atomicAdd(&g_bar_in, 1) == nblocks - 1) {
            g_bar_in = 0;
            __threadfence();
            g_gen = gen + 1;     // release
        } else {
            while (g_gen == gen) { }   // volatile spin
        }
        __threadfence();         // acquire
    }
    __syncthreads();
}

__global__ void __launch_bounds__(BLK, 1)
k_fused(const float* __restrict__ x, const int* __restrict__ src,
        const int* __restrict__ dst,
        const float* __restrict__ W1, const float* __restrict__ b1,
        const float* __restrict__ W2, const float* __restrict__ b2,
        float* __restrict__ out, int n, int e) {
    const int tid  = blockIdx.x * blockDim.x + threadIdx.x;
    const int nthr = gridDim.x * blockDim.x;
    const int nblocks = gridDim.x;

    // ---- phase 1: fill buckets (4 edges/thread, int4 loads) ----------------
    if ((e & 3) == 0) {
        int quads = e >> 2;
        for (int q = tid; q < quads; q += nthr) {
            int base = q * 4;
            int4 s4 = __ldg(reinterpret_cast<const int4*>(src + base));
            int4 d4 = __ldg(reinterpret_cast<const int4*>(dst + base));
            int p0 = atomicAdd(&g_cnt[d4.x], 1);
            int p1 = atomicAdd(&g_cnt[d4.y], 1);
            int p2 = atomicAdd(&g_cnt[d4.z], 1);
            int p3 = atomicAdd(&g_cnt[d4.w], 1);
            if (p0 < CAP) g_bkt[d4.x * CAP + p0] = s4.x;
            if (p1 < CAP) g_bkt[d4.y * CAP + p1] = s4.y;
            if (p2 < CAP) g_bkt[d4.z * CAP + p2] = s4.z;
            if (p3 < CAP) g_bkt[d4.w * CAP + p3] = s4.w;
        }
    } else {
        for (int i = tid; i < e; i += nthr) {
            int d = __ldg(&dst[i]);
            int s = __ldg(&src[i]);
            int slot = atomicAdd(&g_cnt[d], 1);
            if (slot < CAP) g_bkt[d * CAP + slot] = s;
        }
    }
    gbar(nblocks);

    // ---- phase 2: xs = x * dinv (padded 8-float rows) ----------------------
    for (int i = tid; i < n; i += nthr) {
        float dv = rsqrtf((float)(g_cnt[i] + 1));   // +1 self loop
        g_dinv[i] = dv;
        float4 a;
        a.x = __ldg(&x[i * CIN + 0]) * dv;
        a.y = __ldg(&x[i * CIN + 1]) * dv;
        a.z = __ldg(&x[i * CIN + 2]) * dv;
        a.w = __ldg(&x[i * CIN + 3]) * dv;
        float4 b;
        b.x = __ldg(&x[i * CIN + 4]) * dv;
        b.y = 0.f; b.z = 0.f; b.w = 0.f;
        reinterpret_cast<float4*>(&g_xs[i * 8])[0] = a;
        reinterpret_cast<float4*>(&g_xs[i * 8])[1] = b;
    }
    gbar(nblocks);

    // ---- phase 3: gather1 + W1 + relu + W2 (warp per node) -----------------
    {
        int wid = tid >> 5, lane = tid & 31, nwarps = nthr >> 5;
        int o = lane >> 3, f = lane & 7, ob = o * 8;
        for (int i = wid; i < n; i += nwarps) {
            int deg = g_cnt[i];
            if (deg > CAP) deg = CAP;
            const int* row = &g_bkt[i * CAP];
            float acc = (o == 0) ? g_xs[i * 8 + f] : 0.f;   // self loop
            for (int base = 0; base < deg; base += 32) {
                int j = base + ob + f;
                int idx = (j < deg) ? __ldg(&row[j]) : -1;
                int s0 = __shfl_sync(0xffffffffu, idx, ob + 0);
                int s1 = __shfl_sync(0xffffffffu, idx, ob + 1);
                int s2 = __shfl_sync(0xffffffffu, idx, ob + 2);
                int s3 = __shfl_sync(0xffffffffu, idx, ob + 3);
                int s4 = __shfl_sync(0xffffffffu, idx, ob + 4);
                int s5 = __shfl_sync(0xffffffffu, idx, ob + 5);
                int s6 = __shfl_sync(0xffffffffu, idx, ob + 6);
                int s7 = __shfl_sync(0xffffffffu, idx, ob + 7);
                float v0 = (s0 >= 0) ? __ldg(&g_xs[s0 * 8 + f]) : 0.f;
                float v1 = (s1 >= 0) ? __ldg(&g_xs[s1 * 8 + f]) : 0.f;
                float v2 = (s2 >= 0) ? __ldg(&g_xs[s2 * 8 + f]) : 0.f;
                float v3 = (s3 >= 0) ? __ldg(&g_xs[s3 * 8 + f]) : 0.f;
                float v4 = (s4 >= 0) ? __ldg(&g_xs[s4 * 8 + f]) : 0.f;
                float v5 = (s5 >= 0) ? __ldg(&g_xs[s5 * 8 + f]) : 0.f;
                float v6 = (s6 >= 0) ? __ldg(&g_xs[s6 * 8 + f]) : 0.f;
                float v7 = (s7 >= 0) ? __ldg(&g_xs[s7 * 8 + f]) : 0.f;
                acc += ((v0 + v1) + (v2 + v3)) + ((v4 + v5) + (v6 + v7));
            }
            acc += __shfl_down_sync(0xffffffffu, acc, 16);
            acc += __shfl_down_sync(0xffffffffu, acc, 8);
            float a0 = __shfl_sync(0xffffffffu, acc, 0);
            float a1 = __shfl_sync(0xffffffffu, acc, 1);
            float a2 = __shfl_sync(0xffffffffu, acc, 2);
            float a3 = __shfl_sync(0xffffffffu, acc, 3);
            float a4 = __shfl_sync(0xffffffffu, acc, 4);
            float dv = g_dinv[i];
            int k = lane;
            float z = a0 * __ldg(&W1[0 * HID + k]) + a1 * __ldg(&W1[1 * HID + k])
                    + a2 * __ldg(&W1[2 * HID + k]) + a3 * __ldg(&W1[3 * HID + k])
                    + a4 * __ldg(&W1[4 * HID + k]);
            float h = fmaxf(z * dv + __ldg(&b1[k]), 0.f);
            float p = h * __ldg(&W2[k]);
#pragma unroll
            for (int off = 16; off > 0; off >>= 1)
                p += __shfl_xor_sync(0xffffffffu, p, off);
            if (lane == 0) g_t2[i] = p * dv;
        }
    }
    gbar(nblocks);

    // ---- phase 4: gather2 + sigmoid + output; zero g_cnt for next call -----
    {
        int gid = tid >> 2, r = tid & 2, rr = tid & 3, ngroups = nthr >> 2;
        (void)r;
        int lane = tid & 31;
        int qbase = lane & ~3;    // first lane of this quad
        for (int i = gid; i < n; i += ngroups) {
            int degv = (rr == 0) ? g_cnt[i] : 0;
            int deg = __shfl_sync(0xffffffffu, degv, qbase);  // single read/quad
            if (deg > CAP) deg = CAP;
            const int* row = &g_bkt[i * CAP];
            float zacc = (rr == 0) ? g_t2[i] : 0.f;   // self loop
            for (int base = 0; base < deg; base += 32) {
                int j0 = base + rr * 8;
                const int4* rp = reinterpret_cast<const int4*>(&row[j0]);
                int4 ia = __ldg(rp);
                int4 ib = __ldg(rp + 1);
                float v0 = (j0 + 0 < deg) ? __ldg(&g_t2[ia.x]) : 0.f;
                float v1 = (j0 + 1 < deg) ? __ldg(&g_t2[ia.y]) : 0.f;
                float v2 = (j0 + 2 < deg) ? __ldg(&g_t2[ia.z]) : 0.f;
                float v3 = (j0 + 3 < deg) ? __ldg(&g_t2[ia.w]) : 0.f;
                float v4 = (j0 + 4 < deg) ? __ldg(&g_t2[ib.x]) : 0.f;
                float v5 = (j0 + 5 < deg) ? __ldg(&g_t2[ib.y]) : 0.f;
                float v6 = (j0 + 6 < deg) ? __ldg(&g_t2[ib.z]) : 0.f;
                float v7 = (j0 + 7 < deg) ? __ldg(&g_t2[ib.w]) : 0.f;
                zacc += ((v0 + v1) + (v2 + v3)) + ((v4 + v5) + (v6 + v7));
            }
            zacc += __shfl_xor_sync(0xffffffffu, zacc, 2);
            zacc += __shfl_xor_sync(0xffffffffu, zacc, 1);
            if (rr == 0) {
                float v = zacc * g_dinv[i] + __ldg(&b2[0]);
                out[i] = 1.0f / (1.0f + expf(-v));
                g_cnt[i] = 0;            // restore invariant (after last read)
            }
        }
    }
}

extern "C" void kernel_launch(void* const* d_in, const int* in_sizes, int n_in,
                              void* d_out, int out_size) {
    const float* x  = (const float*)d_in[0];
    const int*   ei = (const int*)d_in[1];   // int32 (JAX x64 disabled)
    const float* W1 = (const float*)d_in[2];
    const float* b1 = (const float*)d_in[3];
    const float* W2 = (const float*)d_in[4];
    const float* b2 = (const float*)d_in[5];
    float* out = (float*)d_out;

    int n = in_sizes[0] / CIN;
    int e = in_sizes[1] / 2;
    const int* src = ei;
    const int* dst = ei + e;

    // co-residency-safe grid (host queries only; capture-legal, deterministic)
    int dev = 0, sms = 148, occ = 1;
    cudaGetDevice(&dev);
    cudaDeviceGetAttribute(&sms, cudaDevAttrMultiProcessorCount, dev);
    cudaOccupancyMaxActiveBlocksPerMultiprocessor(&occ, k_fused, BLK, 0);
    if (occ < 1) occ = 1;
    int grid = sms * occ;

    k_fused<<<grid, BLK>>>(x, src, dst, W1, b1, W2, b2, out, n, e);
}

// round 12
// speedup vs baseline: 1.0990x; 1.0990x over previous
#include <cuda_runtime.h>
#include <math.h>

// ---------------------------------------------------------------------------
// CascadeGCN: 2-layer GCN, N=100000, c_in=5, hid=32, c_out=1.
// R12: R9 structure + CAP=96 (128B-aligned rows) + PDL launch overlap +
//      cnt reset folded into gather2 (memset node removed).
// ---------------------------------------------------------------------------

#define NMAX 100000
#define CIN 5
#define HID 32
#define CAP 96    // 384B rows (128B-aligned); Poisson(25): P(deg>=96) ~ 0

__device__ __align__(16) int   g_cnt [NMAX];            // zero at entry/exit
__device__ __align__(16) float g_dinv[NMAX];
__device__ __align__(16) int   g_bkt [NMAX * CAP + 32];
__device__ __align__(16) float g_xs  [NMAX * 8];
__device__ __align__(16) float g_t2  [NMAX];

__device__ __forceinline__ void pdl_trigger() {
    asm volatile("griddepcontrol.launch_dependents;" ::: "memory");
}
__device__ __forceinline__ void pdl_wait() {
    asm volatile("griddepcontrol.wait;" ::: "memory");
}

// --- build buckets: 4 edges/thread (int4), cnt assumed zero at entry --------
__global__ void __launch_bounds__(256)
k_fill(const int* __restrict__ src, const int* __restrict__ dst, int e) {
    int q = blockIdx.x * blockDim.x + threadIdx.x;
    int base = q * 4;
    if (base < e) {
        if (base + 4 <= e) {
            int4 s4 = __ldg(reinterpret_cast<const int4*>(src + base));
            int4 d4 = __ldg(reinterpret_cast<const int4*>(dst + base));
            int p0 = atomicAdd(&g_cnt[d4.x], 1);
            int p1 = atomicAdd(&g_cnt[d4.y], 1);
            int p2 = atomicAdd(&g_cnt[d4.z], 1);
            int p3 = atomicAdd(&g_cnt[d4.w], 1);
            if (p0 < CAP) g_bkt[d4.x * CAP + p0] = s4.x;
            if (p1 < CAP) g_bkt[d4.y * CAP + p1] = s4.y;
            if (p2 < CAP) g_bkt[d4.z * CAP + p2] = s4.z;
            if (p3 < CAP) g_bkt[d4.w * CAP + p3] = s4.w;
        } else {
            for (int i = base; i < e; i++) {
                int d = __ldg(&dst[i]);
                int s = __ldg(&src[i]);
                int slot = atomicAdd(&g_cnt[d], 1);
                if (slot < CAP) g_bkt[d * CAP + slot] = s;
            }
        }
    }
    pdl_trigger();
}

// --- xs = x * dinv (x prefetched before the PDL wait) ----------------------
__global__ void __launch_bounds__(256)
k_prep(const float* __restrict__ x, int n) {
    int i = blockIdx.x * blockDim.x + threadIdx.x;
    float x0 = 0.f, x1 = 0.f, x2 = 0.f, x3 = 0.f, x4 = 0.f;
    if (i < n) {                       // pre-dependency: x is a kernel input
        x0 = __ldg(&x[i * CIN + 0]);
        x1 = __ldg(&x[i * CIN + 1]);
        x2 = __ldg(&x[i * CIN + 2]);
        x3 = __ldg(&x[i * CIN + 3]);
        x4 = __ldg(&x[i * CIN + 4]);
    }
    pdl_wait();                        // g_cnt ready after this
    if (i < n) {
        float dv = rsqrtf((float)(g_cnt[i] + 1));   // +1 self loop
        g_dinv[i] = dv;
        float4 a = make_float4(x0 * dv, x1 * dv, x2 * dv, x3 * dv);
        float4 b = make_float4(x4 * dv, 0.f, 0.f, 0.f);
        reinterpret_cast<float4*>(&g_xs[i * 8])[0] = a;
        reinterpret_cast<float4*>(&g_xs[i * 8])[1] = b;
    }
    pdl_trigger();
}

// --- fused: 5-wide gather -> W1 -> relu -> W2 -> t2 (warp per node) --------
__global__ void __launch_bounds__(256)
k_gather1(const float* __restrict__ W1, const float* __restrict__ b1,
          const float* __restrict__ W2, int n) {
    int t = blockIdx.x * blockDim.x + threadIdx.x;
    int i = t >> 5;
    int lane = t & 31;
    pdl_wait();                        // xs/dinv ready
    if (i < n) {
        int o = lane >> 3;
        int f = lane & 7;
        int ob = o * 8;
        int deg = g_cnt[i];
        if (deg > CAP) deg = CAP;
        const int* row = &g_bkt[i * CAP];

        float acc = (o == 0) ? g_xs[i * 8 + f] : 0.f;   // self loop
        for (int base = 0; base < deg; base += 32) {
            int j = base + ob + f;
            int idx = (j < deg) ? __ldg(&row[j]) : -1;   // 1 coalesced wavefront
            int s0 = __shfl_sync(0xffffffffu, idx, ob + 0);
            int s1 = __shfl_sync(0xffffffffu, idx, ob + 1);
            int s2 = __shfl_sync(0xffffffffu, idx, ob + 2);
            int s3 = __shfl_sync(0xffffffffu, idx, ob + 3);
            int s4 = __shfl_sync(0xffffffffu, idx, ob + 4);
            int s5 = __shfl_sync(0xffffffffu, idx, ob + 5);
            int s6 = __shfl_sync(0xffffffffu, idx, ob + 6);
            int s7 = __shfl_sync(0xffffffffu, idx, ob + 7);
            float v0 = (s0 >= 0) ? __ldg(&g_xs[s0 * 8 + f]) : 0.f;  // 8 in flight
            float v1 = (s1 >= 0) ? __ldg(&g_xs[s1 * 8 + f]) : 0.f;
            float v2 = (s2 >= 0) ? __ldg(&g_xs[s2 * 8 + f]) : 0.f;
            float v3 = (s3 >= 0) ? __ldg(&g_xs[s3 * 8 + f]) : 0.f;
            float v4 = (s4 >= 0) ? __ldg(&g_xs[s4 * 8 + f]) : 0.f;
            float v5 = (s5 >= 0) ? __ldg(&g_xs[s5 * 8 + f]) : 0.f;
            float v6 = (s6 >= 0) ? __ldg(&g_xs[s6 * 8 + f]) : 0.f;
            float v7 = (s7 >= 0) ? __ldg(&g_xs[s7 * 8 + f]) : 0.f;
            acc += ((v0 + v1) + (v2 + v3)) + ((v4 + v5) + (v6 + v7));
        }
        acc += __shfl_down_sync(0xffffffffu, acc, 16);
        acc += __shfl_down_sync(0xffffffffu, acc, 8);
        float a0 = __shfl_sync(0xffffffffu, acc, 0);
        float a1 = __shfl_sync(0xffffffffu, acc, 1);
        float a2 = __shfl_sync(0xffffffffu, acc, 2);
        float a3 = __shfl_sync(0xffffffffu, acc, 3);
        float a4 = __shfl_sync(0xffffffffu, acc, 4);

        float dv = g_dinv[i];
        int k = lane;
        float z = a0 * __ldg(&W1[0 * HID + k]) + a1 * __ldg(&W1[1 * HID + k])
                + a2 * __ldg(&W1[2 * HID + k]) + a3 * __ldg(&W1[3 * HID + k])
                + a4 * __ldg(&W1[4 * HID + k]);
        float h = fmaxf(z * dv + __ldg(&b1[k]), 0.f);
        float p = h * __ldg(&W2[k]);
#pragma unroll
        for (int off = 16; off > 0; off >>= 1)
            p += __shfl_xor_sync(0xffffffffu, p, off);
        if (lane == 0) g_t2[i] = p * dv;
    }
    pdl_trigger();
}

// --- layer-2 gather + sigmoid + output; resets g_cnt (8 nodes/warp) --------
__global__ void __launch_bounds__(256)
k_gather2(float* __restrict__ out, const float* __restrict__ b2, int n) {
    int t = blockIdx.x * blockDim.x + threadIdx.x;
    int i = t >> 2;                 // node (4 lanes per node)
    int r = t & 3;
    pdl_wait();                     // t2 ready
    if (i < n) {
        int deg = g_cnt[i];
        if (deg > CAP) deg = CAP;
        const int* row = &g_bkt[i * CAP];

        float z = (r == 0) ? g_t2[i] : 0.f;    // self loop
        for (int base = 0; base < deg; base += 32) {
            int j0 = base + r * 8;
            const int4* rp = reinterpret_cast<const int4*>(&row[j0]);
            int4 ia = __ldg(rp);                // safe: g_bkt padded +32
            int4 ib = __ldg(rp + 1);
            float v0 = (j0 + 0 < deg) ? __ldg(&g_t2[ia.x]) : 0.f;  // 8 in flight
            float v1 = (j0 + 1 < deg) ? __ldg(&g_t2[ia.y]) : 0.f;
            float v2 = (j0 + 2 < deg) ? __ldg(&g_t2[ia.z]) : 0.f;
            float v3 = (j0 + 3 < deg) ? __ldg(&g_t2[ia.w]) : 0.f;
            float v4 = (j0 + 4 < deg) ? __ldg(&g_t2[ib.x]) : 0.f;
            float v5 = (j0 + 5 < deg) ? __ldg(&g_t2[ib.y]) : 0.f;
            float v6 = (j0 + 6 < deg) ? __ldg(&g_t2[ib.z]) : 0.f;
            float v7 = (j0 + 7 < deg) ? __ldg(&g_t2[ib.w]) : 0.f;
            z += ((v0 + v1) + (v2 + v3)) + ((v4 + v5) + (v6 + v7));
        }
        z += __shfl_xor_sync(0xffffffffu, z, 2);
        z += __shfl_xor_sync(0xffffffffu, z, 1);
        if (r == 0) {
            float v = z * g_dinv[i] + __ldg(&b2[0]);
            out[i] = 1.0f / (1.0f + expf(-v));
            g_cnt[i] = 0;           // restore invariant for next call
        }
    }
}

static void launch_pdl(void* func, dim3 grid, dim3 block,
                       void** args) {
    cudaLaunchConfig_t cfg = {};
    cfg.gridDim = grid;
    cfg.blockDim = block;
    cfg.dynamicSmemBytes = 0;
    cfg.stream = 0;
    cudaLaunchAttribute attr[1];
    attr[0].id = cudaLaunchAttributeProgrammaticStreamSerialization;
    attr[0].val.programmaticStreamSerializationAllowed = 1;
    cfg.attrs = attr;
    cfg.numAttrs = 1;
    cudaLaunchKernelExC(&cfg, func, args);
}

extern "C" void kernel_launch(void* const* d_in, const int* in_sizes, int n_in,
                              void* d_out, int out_size) {
    const float* x  = (const float*)d_in[0];
    const int*   ei = (const int*)d_in[1];   // int32 (JAX x64 disabled)
    const float* W1 = (const float*)d_in[2];
    const float* b1 = (const float*)d_in[3];
    const float* W2 = (const float*)d_in[4];
    const float* b2 = (const float*)d_in[5];
    float* out = (float*)d_out;

    int n = in_sizes[0] / CIN;
    int e = in_sizes[1] / 2;
    const int* src = ei;
    const int* dst = ei + e;

    const int B = 256;
    int gridN  = (n + B - 1) / B;
    int gridE4 = (e + B * 4 - 1) / (B * 4);
    long long tn32 = (long long)n * 32;
    long long tn4  = (long long)n * 4;
    int gridN32 = (int)((tn32 + B - 1) / B);
    int gridN4  = (int)((tn4  + B - 1) / B);

    k_fill<<<gridE4, B>>>(src, dst, e);

    {   // prep (PDL-dependent on fill)
        void* args[] = { (void*)&x, (void*)&n };
        launch_pdl((void*)k_prep, dim3(gridN), dim3(B), args);
    }
    {   // gather1 (PDL-dependent on prep)
        void* args[] = { (void*)&W1, (void*)&b1, (void*)&W2, (void*)&n };
        launch_pdl((void*)k_gather1, dim3(gridN32), dim3(B), args);
    }
    {   // gather2 (PDL-dependent on gather1)
        void* args[] = { (void*)&out, (void*)&b2, (void*)&n };
        launch_pdl((void*)k_gather2, dim3(gridN4), dim3(B), args);
    }
}

// round 13
// speedup vs baseline: 1.1297x; 1.0280x over previous
#include <cuda_runtime.h>
#include <math.h>

// ---------------------------------------------------------------------------
// CascadeGCN: 2-layer GCN, N=100000, c_in=5, hid=32, c_out=1.
// R13: R9 structure (best so far) + memset node removed (g_cnt reset in
//      gather2) + fill with 8-edge ILP.
// ---------------------------------------------------------------------------

#define NMAX 100000
#define CIN 5
#define HID 32
#define CAP 192   // proven best (R9); Poisson(25): P(deg>=192) ~ e^-224

__device__ __align__(16) int   g_cnt [NMAX];            // zero at entry/exit
__device__ __align__(16) float g_dinv[NMAX];
__device__ __align__(16) int   g_bkt [NMAX * CAP + 32]; // +32 pad for int4 reads
__device__ __align__(16) float g_xs  [NMAX * 8];        // x*dinv, 32B rows
__device__ __align__(16) float g_t2  [NMAX];            // dv*(h1@W2)

// --- build buckets: 8 edges/thread (2x int4), 8 atomic->store chains -------
__global__ void __launch_bounds__(256)
k_fill(const int* __restrict__ src, const int* __restrict__ dst, int e) {
    int q = blockIdx.x * blockDim.x + threadIdx.x;
    int base = q * 8;
    if (base >= e) return;
    if (base + 8 <= e) {
        int4 sa = __ldg(reinterpret_cast<const int4*>(src + base));
        int4 sb = __ldg(reinterpret_cast<const int4*>(src + base + 4));
        int4 da = __ldg(reinterpret_cast<const int4*>(dst + base));
        int4 db = __ldg(reinterpret_cast<const int4*>(dst + base + 4));
        int p0 = atomicAdd(&g_cnt[da.x], 1);   // 8 atomics in flight
        int p1 = atomicAdd(&g_cnt[da.y], 1);
        int p2 = atomicAdd(&g_cnt[da.z], 1);
        int p3 = atomicAdd(&g_cnt[da.w], 1);
        int p4 = atomicAdd(&g_cnt[db.x], 1);
        int p5 = atomicAdd(&g_cnt[db.y], 1);
        int p6 = atomicAdd(&g_cnt[db.z], 1);
        int p7 = atomicAdd(&g_cnt[db.w], 1);
        if (p0 < CAP) g_bkt[da.x * CAP + p0] = sa.x;
        if (p1 < CAP) g_bkt[da.y * CAP + p1] = sa.y;
        if (p2 < CAP) g_bkt[da.z * CAP + p2] = sa.z;
        if (p3 < CAP) g_bkt[da.w * CAP + p3] = sa.w;
        if (p4 < CAP) g_bkt[db.x * CAP + p4] = sb.x;
        if (p5 < CAP) g_bkt[db.y * CAP + p5] = sb.y;
        if (p6 < CAP) g_bkt[db.z * CAP + p6] = sb.z;
        if (p7 < CAP) g_bkt[db.w * CAP + p7] = sb.w;
    } else {
        for (int i = base; i < e; i++) {
            int d = __ldg(&dst[i]);
            int s = __ldg(&src[i]);
            int slot = atomicAdd(&g_cnt[d], 1);
            if (slot < CAP) g_bkt[d * CAP + slot] = s;
        }
    }
}

// --- xs = x * dinv, padded to 8 floats (thread per node) -------------------
__global__ void __launch_bounds__(256)
k_prep(const float* __restrict__ x, int n) {
    int i = blockIdx.x * blockDim.x + threadIdx.x;
    if (i >= n) return;
    float dv = rsqrtf((float)(g_cnt[i] + 1));   // +1 self loop
    g_dinv[i] = dv;
    float4 a;
    a.x = __ldg(&x[i * CIN + 0]) * dv;
    a.y = __ldg(&x[i * CIN + 1]) * dv;
    a.z = __ldg(&x[i * CIN + 2]) * dv;
    a.w = __ldg(&x[i * CIN + 3]) * dv;
    float4 b;
    b.x = __ldg(&x[i * CIN + 4]) * dv;
    b.y = 0.f; b.z = 0.f; b.w = 0.f;
    reinterpret_cast<float4*>(&g_xs[i * 8])[0] = a;
    reinterpret_cast<float4*>(&g_xs[i * 8])[1] = b;
}

// --- fused: 5-wide gather -> W1 -> relu -> W2 -> t2 (warp per node) --------
// 32-edge windows. Octet o, lane f. Index load coalesced across the warp;
// each octet walks its 8 indices via shfl -> 8 value loads in flight.
__global__ void __launch_bounds__(256)
k_gather1(const float* __restrict__ W1, const float* __restrict__ b1,
          const float* __restrict__ W2, int n) {
    int t = blockIdx.x * blockDim.x + threadIdx.x;
    int i = t >> 5;
    int lane = t & 31;
    if (i >= n) return;
    int o = lane >> 3;
    int f = lane & 7;
    int ob = o * 8;
    int deg = g_cnt[i];
    if (deg > CAP) deg = CAP;
    const int* row = &g_bkt[i * CAP];

    float acc = (o == 0) ? g_xs[i * 8 + f] : 0.f;   // self loop
    for (int base = 0; base < deg; base += 32) {
        int j = base + ob + f;
        int idx = (j < deg) ? __ldg(&row[j]) : -1;   // 1 coalesced wavefront
        int s0 = __shfl_sync(0xffffffffu, idx, ob + 0);
        int s1 = __shfl_sync(0xffffffffu, idx, ob + 1);
        int s2 = __shfl_sync(0xffffffffu, idx, ob + 2);
        int s3 = __shfl_sync(0xffffffffu, idx, ob + 3);
        int s4 = __shfl_sync(0xffffffffu, idx, ob + 4);
        int s5 = __shfl_sync(0xffffffffu, idx, ob + 5);
        int s6 = __shfl_sync(0xffffffffu, idx, ob + 6);
        int s7 = __shfl_sync(0xffffffffu, idx, ob + 7);
        float v0 = (s0 >= 0) ? __ldg(&g_xs[s0 * 8 + f]) : 0.f;  // 8 in flight
        float v1 = (s1 >= 0) ? __ldg(&g_xs[s1 * 8 + f]) : 0.f;
        float v2 = (s2 >= 0) ? __ldg(&g_xs[s2 * 8 + f]) : 0.f;
        float v3 = (s3 >= 0) ? __ldg(&g_xs[s3 * 8 + f]) : 0.f;
        float v4 = (s4 >= 0) ? __ldg(&g_xs[s4 * 8 + f]) : 0.f;
        float v5 = (s5 >= 0) ? __ldg(&g_xs[s5 * 8 + f]) : 0.f;
        float v6 = (s6 >= 0) ? __ldg(&g_xs[s6 * 8 + f]) : 0.f;
        float v7 = (s7 >= 0) ? __ldg(&g_xs[s7 * 8 + f]) : 0.f;
        acc += ((v0 + v1) + (v2 + v3)) + ((v4 + v5) + (v6 + v7));
    }
    acc += __shfl_down_sync(0xffffffffu, acc, 16);
    acc += __shfl_down_sync(0xffffffffu, acc, 8);
    float a0 = __shfl_sync(0xffffffffu, acc, 0);
    float a1 = __shfl_sync(0xffffffffu, acc, 1);
    float a2 = __shfl_sync(0xffffffffu, acc, 2);
    float a3 = __shfl_sync(0xffffffffu, acc, 3);
    float a4 = __shfl_sync(0xffffffffu, acc, 4);

    float dv = g_dinv[i];
    int k = lane;
    float z = a0 * __ldg(&W1[0 * HID + k]) + a1 * __ldg(&W1[1 * HID + k])
            + a2 * __ldg(&W1[2 * HID + k]) + a3 * __ldg(&W1[3 * HID + k])
            + a4 * __ldg(&W1[4 * HID + k]);
    float h = fmaxf(z * dv + __ldg(&b1[k]), 0.f);
    float p = h * __ldg(&W2[k]);
#pragma unroll
    for (int off = 16; off > 0; off >>= 1)
        p += __shfl_xor_sync(0xffffffffu, p, off);
    if (lane == 0) g_t2[i] = p * dv;
}

// --- layer-2 gather + sigmoid + output; resets g_cnt (8 nodes/warp) --------
__global__ void __launch_bounds__(256)
k_gather2(float* __restrict__ out, const float* __restrict__ b2, int n) {
    int t = blockIdx.x * blockDim.x + threadIdx.x;
    int i = t >> 2;                 // node (4 lanes per node)
    int r = t & 3;
    if (i >= n) return;
    int deg = g_cnt[i];
    if (deg > CAP) deg = CAP;
    const int* row = &g_bkt[i * CAP];

    float z = (r == 0) ? g_t2[i] : 0.f;    // self loop
    for (int base = 0; base < deg; base += 32) {
        int j0 = base + r * 8;
        const int4* rp = reinterpret_cast<const int4*>(&row[j0]);
        int4 ia = __ldg(rp);                // safe: g_bkt padded +32
        int4 ib = __ldg(rp + 1);
        float v0 = (j0 + 0 < deg) ? __ldg(&g_t2[ia.x]) : 0.f;  // 8 in flight
        float v1 = (j0 + 1 < deg) ? __ldg(&g_t2[ia.y]) : 0.f;
        float v2 = (j0 + 2 < deg) ? __ldg(&g_t2[ia.z]) : 0.f;
        float v3 = (j0 + 3 < deg) ? __ldg(&g_t2[ia.w]) : 0.f;
        float v4 = (j0 + 4 < deg) ? __ldg(&g_t2[ib.x]) : 0.f;
        float v5 = (j0 + 5 < deg) ? __ldg(&g_t2[ib.y]) : 0.f;
        float v6 = (j0 + 6 < deg) ? __ldg(&g_t2[ib.z]) : 0.f;
        float v7 = (j0 + 7 < deg) ? __ldg(&g_t2[ib.w]) : 0.f;
        z += ((v0 + v1) + (v2 + v3)) + ((v4 + v5) + (v6 + v7));
    }
    z += __shfl_xor_sync(0xffffffffu, z, 2);
    z += __shfl_xor_sync(0xffffffffu, z, 1);
    if (r == 0) {
        float v = z * g_dinv[i] + __ldg(&b2[0]);
        out[i] = 1.0f / (1.0f + expf(-v));
        g_cnt[i] = 0;               // restore invariant for next call
    }
}

extern "C" void kernel_launch(void* const* d_in, const int* in_sizes, int n_in,
                              void* d_out, int out_size) {
    const float* x  = (const float*)d_in[0];
    const int*   ei = (const int*)d_in[1];   // int32 (JAX x64 disabled)
    const float* W1 = (const float*)d_in[2];
    const float* b1 = (const float*)d_in[3];
    const float* W2 = (const float*)d_in[4];
    const float* b2 = (const float*)d_in[5];
    float* out = (float*)d_out;

    int n = in_sizes[0] / CIN;
    int e = in_sizes[1] / 2;
    const int* src = ei;
    const int* dst = ei + e;

    const int B = 256;
    int gridN  = (n + B - 1) / B;
    int gridE8 = (e + B * 8 - 1) / (B * 8);
    long long tn32 = (long long)n * 32;
    long long tn4  = (long long)n * 4;
    int gridN32 = (int)((tn32 + B - 1) / B);
    int gridN4  = (int)((tn4  + B - 1) / B);

    k_fill   <<<gridE8,  B>>>(src, dst, e);
    k_prep   <<<gridN,   B>>>(x, n);
    k_gather1<<<gridN32, B>>>(W1, b1, W2, n);
    k_gather2<<<gridN4,  B>>>(out, b2, n);
}

// round 14
// speedup vs baseline: 1.1455x; 1.0140x over previous
#include <cuda_runtime.h>
#include <math.h>

// ---------------------------------------------------------------------------
// CascadeGCN: 2-layer GCN, N=100000, c_in=5, hid=32, c_out=1.
// R14: R9 base + persistent exact-one-wave grids (kills wave-quantization
//      tails on fill/gather1/gather2) + memset node removed (cnt reset in
//      gather2 tail).
// ---------------------------------------------------------------------------

#define NMAX 100000
#define CIN 5
#define HID 32
#define CAP 192   // proven best (R9)

__device__ __align__(16) int   g_cnt [NMAX];            // zero at entry/exit
__device__ __align__(16) float g_dinv[NMAX];
__device__ __align__(16) int   g_bkt [NMAX * CAP + 32]; // +32 pad for int4 reads
__device__ __align__(16) float g_xs  [NMAX * 8];        // x*dinv, 32B rows
__device__ __align__(16) float g_t2  [NMAX];            // dv*(h1@W2)

// --- build buckets: grid-stride, 4 edges/iteration (int4) -------------------
__global__ void __launch_bounds__(256)
k_fill(const int* __restrict__ src, const int* __restrict__ dst, int e) {
    int tid  = blockIdx.x * blockDim.x + threadIdx.x;
    int nthr = gridDim.x * blockDim.x;
    int quads = e >> 2;
    for (int q = tid; q < quads; q += nthr) {
        int base = q * 4;
        int4 s4 = __ldg(reinterpret_cast<const int4*>(src + base));
        int4 d4 = __ldg(reinterpret_cast<const int4*>(dst + base));
        int p0 = atomicAdd(&g_cnt[d4.x], 1);   // 4 atomics in flight
        int p1 = atomicAdd(&g_cnt[d4.y], 1);
        int p2 = atomicAdd(&g_cnt[d4.z], 1);
        int p3 = atomicAdd(&g_cnt[d4.w], 1);
        if (p0 < CAP) g_bkt[d4.x * CAP + p0] = s4.x;
        if (p1 < CAP) g_bkt[d4.y * CAP + p1] = s4.y;
        if (p2 < CAP) g_bkt[d4.z * CAP + p2] = s4.z;
        if (p3 < CAP) g_bkt[d4.w * CAP + p3] = s4.w;
    }
    // tail edges (e % 4), handled by thread 0 only
    if (tid == 0) {
        for (int i = quads * 4; i < e; i++) {
            int d = __ldg(&dst[i]);
            int s = __ldg(&src[i]);
            int slot = atomicAdd(&g_cnt[d], 1);
            if (slot < CAP) g_bkt[d * CAP + slot] = s;
        }
    }
}

// --- xs = x * dinv, padded to 8 floats (thread per node, 1 wave) -----------
__global__ void __launch_bounds__(256)
k_prep(const float* __restrict__ x, int n) {
    int i = blockIdx.x * blockDim.x + threadIdx.x;
    if (i >= n) return;
    float dv = rsqrtf((float)(g_cnt[i] + 1));   // +1 self loop
    g_dinv[i] = dv;
    float4 a;
    a.x = __ldg(&x[i * CIN + 0]) * dv;
    a.y = __ldg(&x[i * CIN + 1]) * dv;
    a.z = __ldg(&x[i * CIN + 2]) * dv;
    a.w = __ldg(&x[i * CIN + 3]) * dv;
    float4 b;
    b.x = __ldg(&x[i * CIN + 4]) * dv;
    b.y = 0.f; b.z = 0.f; b.w = 0.f;
    reinterpret_cast<float4*>(&g_xs[i * 8])[0] = a;
    reinterpret_cast<float4*>(&g_xs[i * 8])[1] = b;
}

// --- fused: 5-wide gather -> W1 -> relu -> W2 -> t2 (warp/node, stride) ----
__global__ void __launch_bounds__(256)
k_gather1(const float* __restrict__ W1, const float* __restrict__ b1,
          const float* __restrict__ W2, int n) {
    int t = blockIdx.x * blockDim.x + threadIdx.x;
    int wid = t >> 5;
    int lane = t & 31;
    int nwarps = (gridDim.x * blockDim.x) >> 5;
    int o = lane >> 3;
    int f = lane & 7;
    int ob = o * 8;
    for (int i = wid; i < n; i += nwarps) {
        int deg = g_cnt[i];
        if (deg > CAP) deg = CAP;
        const int* row = &g_bkt[i * CAP];

        float acc = (o == 0) ? g_xs[i * 8 + f] : 0.f;   // self loop
        for (int base = 0; base < deg; base += 32) {
            int j = base + ob + f;
            int idx = (j < deg) ? __ldg(&row[j]) : -1;   // 1 coalesced wavefront
            int s0 = __shfl_sync(0xffffffffu, idx, ob + 0);
            int s1 = __shfl_sync(0xffffffffu, idx, ob + 1);
            int s2 = __shfl_sync(0xffffffffu, idx, ob + 2);
            int s3 = __shfl_sync(0xffffffffu, idx, ob + 3);
            int s4 = __shfl_sync(0xffffffffu, idx, ob + 4);
            int s5 = __shfl_sync(0xffffffffu, idx, ob + 5);
            int s6 = __shfl_sync(0xffffffffu, idx, ob + 6);
            int s7 = __shfl_sync(0xffffffffu, idx, ob + 7);
            float v0 = (s0 >= 0) ? __ldg(&g_xs[s0 * 8 + f]) : 0.f;  // 8 in flight
            float v1 = (s1 >= 0) ? __ldg(&g_xs[s1 * 8 + f]) : 0.f;
            float v2 = (s2 >= 0) ? __ldg(&g_xs[s2 * 8 + f]) : 0.f;
            float v3 = (s3 >= 0) ? __ldg(&g_xs[s3 * 8 + f]) : 0.f;
            float v4 = (s4 >= 0) ? __ldg(&g_xs[s4 * 8 + f]) : 0.f;
            float v5 = (s5 >= 0) ? __ldg(&g_xs[s5 * 8 + f]) : 0.f;
            float v6 = (s6 >= 0) ? __ldg(&g_xs[s6 * 8 + f]) : 0.f;
            float v7 = (s7 >= 0) ? __ldg(&g_xs[s7 * 8 + f]) : 0.f;
            acc += ((v0 + v1) + (v2 + v3)) + ((v4 + v5) + (v6 + v7));
        }
        acc += __shfl_down_sync(0xffffffffu, acc, 16);
        acc += __shfl_down_sync(0xffffffffu, acc, 8);
        float a0 = __shfl_sync(0xffffffffu, acc, 0);
        float a1 = __shfl_sync(0xffffffffu, acc, 1);
        float a2 = __shfl_sync(0xffffffffu, acc, 2);
        float a3 = __shfl_sync(0xffffffffu, acc, 3);
        float a4 = __shfl_sync(0xffffffffu, acc, 4);

        float dv = g_dinv[i];
        int k = lane;
        float z = a0 * __ldg(&W1[0 * HID + k]) + a1 * __ldg(&W1[1 * HID + k])
                + a2 * __ldg(&W1[2 * HID + k]) + a3 * __ldg(&W1[3 * HID + k])
                + a4 * __ldg(&W1[4 * HID + k]);
        float h = fmaxf(z * dv + __ldg(&b1[k]), 0.f);
        float p = h * __ldg(&W2[k]);
#pragma unroll
        for (int off = 16; off > 0; off >>= 1)
            p += __shfl_xor_sync(0xffffffffu, p, off);
        if (lane == 0) g_t2[i] = p * dv;
    }
}

// --- layer-2 gather + sigmoid + output; resets g_cnt (grid-stride) ---------
__global__ void __launch_bounds__(256)
k_gather2(float* __restrict__ out, const float* __restrict__ b2, int n) {
    int t = blockIdx.x * blockDim.x + threadIdx.x;
    int gid = t >> 2;               // node group (4 lanes per node)
    int r = t & 3;
    int ngroups = (gridDim.x * blockDim.x) >> 2;
    for (int i = gid; i < n; i += ngroups) {
        int deg = g_cnt[i];
        if (deg > CAP) deg = CAP;
        const int* row = &g_bkt[i * CAP];

        float z = (r == 0) ? g_t2[i] : 0.f;    // self loop
        for (int base = 0; base < deg; base += 32) {
            int j0 = base + r * 8;
            const int4* rp = reinterpret_cast<const int4*>(&row[j0]);
            int4 ia = __ldg(rp);                // safe: g_bkt padded +32
            int4 ib = __ldg(rp + 1);
            float v0 = (j0 + 0 < deg) ? __ldg(&g_t2[ia.x]) : 0.f;  // 8 in flight
            float v1 = (j0 + 1 < deg) ? __ldg(&g_t2[ia.y]) : 0.f;
            float v2 = (j0 + 2 < deg) ? __ldg(&g_t2[ia.z]) : 0.f;
            float v3 = (j0 + 3 < deg) ? __ldg(&g_t2[ia.w]) : 0.f;
            float v4 = (j0 + 4 < deg) ? __ldg(&g_t2[ib.x]) : 0.f;
            float v5 = (j0 + 5 < deg) ? __ldg(&g_t2[ib.y]) : 0.f;
            float v6 = (j0 + 6 < deg) ? __ldg(&g_t2[ib.z]) : 0.f;
            float v7 = (j0 + 7 < deg) ? __ldg(&g_t2[ib.w]) : 0.f;
            z += ((v0 + v1) + (v2 + v3)) + ((v4 + v5) + (v6 + v7));
        }
        z += __shfl_xor_sync(0xffffffffu, z, 2);
        z += __shfl_xor_sync(0xffffffffu, z, 1);
        if (r == 0) {
            float v = z * g_dinv[i] + __ldg(&b2[0]);
            out[i] = 1.0f / (1.0f + expf(-v));
            g_cnt[i] = 0;           // restore invariant for next call
        }
    }
}

extern "C" void kernel_launch(void* const* d_in, const int* in_sizes, int n_in,
                              void* d_out, int out_size) {
    const float* x  = (const float*)d_in[0];
    const int*   ei = (const int*)d_in[1];   // int32 (JAX x64 disabled)
    const float* W1 = (const float*)d_in[2];
    const float* b1 = (const float*)d_in[3];
    const float* W2 = (const float*)d_in[4];
    const float* b2 = (const float*)d_in[5];
    float* out = (float*)d_out;

    int n = in_sizes[0] / CIN;
    int e = in_sizes[1] / 2;
    const int* src = ei;
    const int* dst = ei + e;

    const int B = 256;

    // exact one-wave grids (host occupancy queries: capture-safe, deterministic)
    int dev = 0, sms = 148;
    cudaGetDevice(&dev);
    cudaDeviceGetAttribute(&sms, cudaDevAttrMultiProcessorCount, dev);
    int occF = 1, occG1 = 1, occG2 = 1;
    cudaOccupancyMaxActiveBlocksPerMultiprocessor(&occF,  k_fill,    B, 0);
    cudaOccupancyMaxActiveBlocksPerMultiprocessor(&occG1, k_gather1, B, 0);
    cudaOccupancyMaxActiveBlocksPerMultiprocessor(&occG2, k_gather2, B, 0);
    if (occF  < 1) occF  = 1;
    if (occG1 < 1) occG1 = 1;
    if (occG2 < 1) occG2 = 1;

    int gridN = (n + B - 1) / B;
    // cap persistent grids at the work size
    long long needF  = ((long long)(e >> 2) + B - 1) / B;
    long long needG1 = ((long long)n * 32 + B - 1) / B;
    long long needG2 = ((long long)n * 4  + B - 1) / B;
    int gridF  = (int)((needF  < (long long)sms * occF ) ? needF  : (long long)sms * occF);
    int gridG1 = (int)((needG1 < (long long)sms * occG1) ? needG1 : (long long)sms * occG1);
    int gridG2 = (int)((needG2 < (long long)sms * occG2) ? needG2 : (long long)sms * occG2);
    if (gridF < 1) gridF = 1;

    k_fill   <<<gridF,  B>>>(src, dst, e);
    k_prep   <<<gridN,  B>>>(x, n);
    k_gather1<<<gridG1, B>>>(W1, b1, W2, n);
    k_gather2<<<gridG2, B>>>(out, b2, n);
}